// round 1
// baseline (speedup 1.0000x reference)
#include <cuda_runtime.h>
#include <math.h>

#define HW   4096
#define WD   64
#define C    256
#define B    16
#define NO   260   // 256 ctx channels + 4 gate channels

// ---------------- scratch (static device globals; no allocs) ----------------
__device__ float g_t[B * NO * HW];       // conv1x1 output: ctx(256) + gates(4)
__device__ float g_ctxall[B * C * HW];   // ctx_all
__device__ float g_klog[B * HW];
__device__ float g_k[B * HW];
__device__ float g_qk[B * C];
__device__ float g_v[B * C];

// ---------------- f32x2 helpers (FFMA2: 2 fp32 FMA per instruction) ---------
__device__ __forceinline__ unsigned long long pk2(float lo, float hi) {
    unsigned long long r;
    asm("mov.b64 %0,{%1,%2};" : "=l"(r) : "f"(lo), "f"(hi));
    return r;
}
__device__ __forceinline__ void upk2(unsigned long long v, float& lo, float& hi) {
    asm("mov.b64 {%0,%1},%2;" : "=f"(lo), "=f"(hi) : "l"(v));
}
__device__ __forceinline__ void fma2(unsigned long long& d, unsigned long long a,
                                     unsigned long long b) {
    asm("fma.rn.f32x2 %0,%1,%2,%0;" : "+l"(d) : "l"(a), "l"(b));
}

// =====================================================================
// K1: conv1x1  t[b,o,hw] = sum_c x[b,c,hw]*w[o,c] + bias[o]
// CTA = 64 pixels x all 260 (pad 272) outputs. f32x2 over pixel pairs.
// Weights stored pre-splatted (both halves identical) in SMEM.
// =====================================================================
#define KC 16
__global__ __launch_bounds__(256, 2) void k_conv1x1(const float* __restrict__ x,
                                                    const float* __restrict__ w,
                                                    const float* __restrict__ bias) {
    __shared__ float xs[KC][64];
    __shared__ unsigned long long ws[272 * 18];   // [o][k] splatted, stride 18
    const int tid  = threadIdx.x;
    const int b    = blockIdx.x >> 6;
    const int pix0 = (blockIdx.x & 63) << 6;
    const int ty = tid >> 4, tx = tid & 15;

    unsigned long long acc[17][2];
#pragma unroll
    for (int j = 0; j < 17; j++) { acc[j][0] = 0ull; acc[j][1] = 0ull; }

    for (int k0 = 0; k0 < C; k0 += KC) {
        __syncthreads();
#pragma unroll
        for (int it = 0; it < 4; it++) {
            int idx = tid + it * 256;          // < 1024
            int r = idx >> 6, cc = idx & 63;
            xs[r][cc] = x[((b * C + k0 + r) << 12) + pix0 + cc];
        }
#pragma unroll
        for (int it = 0; it < 17; it++) {
            int idx = tid + it * 256;          // < 4352
            int o = idx >> 4, kk = idx & 15;
            float wv = (o < NO) ? w[o * C + k0 + kk] : 0.f;
            ws[o * 18 + kk] = pk2(wv, wv);
        }
        __syncthreads();
#pragma unroll
        for (int kk = 0; kk < KC; kk += 2) {
            float4 a0 = *(const float4*)&xs[kk][tx << 2];
            float4 a1 = *(const float4*)&xs[kk + 1][tx << 2];
            unsigned long long a0l = pk2(a0.x, a0.y), a0h = pk2(a0.z, a0.w);
            unsigned long long a1l = pk2(a1.x, a1.y), a1h = pk2(a1.z, a1.w);
#pragma unroll
            for (int j = 0; j < 17; j++) {
                ulonglong2 wv = *(const ulonglong2*)&ws[(ty * 17 + j) * 18 + kk];
                fma2(acc[j][0], a0l, wv.x);
                fma2(acc[j][1], a0h, wv.x);
                fma2(acc[j][0], a1l, wv.y);
                fma2(acc[j][1], a1h, wv.y);
            }
        }
    }
#pragma unroll
    for (int j = 0; j < 17; j++) {
        int o = ty * 17 + j;
        if (o < NO) {
            float bv = bias[o];
            float4 r;
            upk2(acc[j][0], r.x, r.y);
            upk2(acc[j][1], r.z, r.w);
            r.x += bv; r.y += bv; r.z += bv; r.w += bv;
            *(float4*)&g_t[((b * NO + o) << 12) + pix0 + (tx << 2)] = r;
        }
    }
}

// =====================================================================
// K2: fused dw3->gelu -> dw5->gelu -> dw7->gelu chain + gated accumulate
//     + global-context term, one CTA per (b, channel) 64x64 plane.
// =====================================================================
__device__ __forceinline__ float gelu_exact(float v) {
    return 0.5f * v * (1.f + erff(v * 0.70710678118654752440f));
}

#define PST 72   // padded row stride (70 rows x 72 cols, halo = 3)

template <int KS>
__device__ __forceinline__ void stage(const float* __restrict__ s_in,
                                      float* __restrict__ s_out,
                                      const float* __restrict__ sW,
                                      int r, int cs) {
    const int P = KS / 2;
    float acc[16];
#pragma unroll
    for (int i = 0; i < 16; i++) acc[i] = 0.f;
#pragma unroll
    for (int dy = 0; dy < KS; dy++) {
        float row[16 + 2 * (KS / 2)];
        const float* rp = &s_in[(r + 3 + dy - P) * PST + (cs + 3 - P)];
#pragma unroll
        for (int i = 0; i < 16 + 2 * P; i++) row[i] = rp[i];
#pragma unroll
        for (int dx = 0; dx < KS; dx++) {
            float wv = sW[dy * KS + dx];
#pragma unroll
            for (int i = 0; i < 16; i++) acc[i] += row[i + dx] * wv;
        }
    }
    float* op = &s_out[(r + 3) * PST + cs + 3];
#pragma unroll
    for (int i = 0; i < 16; i++) op[i] = gelu_exact(acc[i]);
}

__global__ __launch_bounds__(256) void k_dwchain(const float* __restrict__ fw3,
                                                 const float* __restrict__ fw5,
                                                 const float* __restrict__ fw7) {
    __shared__ float sA[70 * PST];
    __shared__ float sB[70 * PST];
    __shared__ float sW[49];
    __shared__ float sRed[8];
    const int tid = threadIdx.x;
    const int b  = blockIdx.x >> 8;
    const int ch = blockIdx.x & 255;
    const int r  = tid >> 2;            // 0..63
    const int cs = (tid & 3) << 4;      // 0,16,32,48

    for (int i = tid; i < 70 * PST; i += 256) { sA[i] = 0.f; sB[i] = 0.f; }
    __syncthreads();

    const float* src = &g_t[(b * NO + ch) << 12];
#pragma unroll
    for (int i = 0; i < 16; i++) {
        int idx = tid + i * 256;
        int rr = idx >> 6, cc = idx & 63;
        sA[(rr + 3) * PST + cc + 3] = src[idx];
    }

    const float* gbase = &g_t[(b * NO + C) << 12];  // gate planes, 4 x 4096
    float accAll[16];
#pragma unroll
    for (int i = 0; i < 16; i++) accAll[i] = 0.f;

    // ---- stage 1: 3x3 ----
    if (tid < 9) sW[tid] = fw3[ch * 9 + tid];
    __syncthreads();
    stage<3>(sA, sB, sW, r, cs);
#pragma unroll
    for (int i = 0; i < 16; i++) {
        int pix = r * 64 + cs + i;
        accAll[i] += sB[(r + 3) * PST + cs + 3 + i] * gbase[pix];
    }
    __syncthreads();
    // ---- stage 2: 5x5 ----
    if (tid < 25) sW[tid] = fw5[ch * 25 + tid];
    __syncthreads();
    stage<5>(sB, sA, sW, r, cs);
#pragma unroll
    for (int i = 0; i < 16; i++) {
        int pix = r * 64 + cs + i;
        accAll[i] += sA[(r + 3) * PST + cs + 3 + i] * gbase[HW + pix];
    }
    __syncthreads();
    // ---- stage 3: 7x7 ----
    if (tid < 49) sW[tid] = fw7[ch * 49 + tid];
    __syncthreads();
    stage<7>(sA, sB, sW, r, cs);
    float lsum = 0.f;
#pragma unroll
    for (int i = 0; i < 16; i++) {
        int pix = r * 64 + cs + i;
        float v = sB[(r + 3) * PST + cs + 3 + i];
        accAll[i] += v * gbase[2 * HW + pix];
        lsum += v;
    }
    // block reduce lsum -> mean of final ctx plane
    for (int off = 16; off; off >>= 1)
        lsum += __shfl_xor_sync(0xffffffffu, lsum, off);
    if ((tid & 31) == 0) sRed[tid >> 5] = lsum;
    __syncthreads();
    float tot = 0.f;
#pragma unroll
    for (int i = 0; i < 8; i++) tot += sRed[i];
    const float mean = tot * (1.f / 4096.f);

    float* dst = &g_ctxall[((b * C + ch) << 12) + r * 64 + cs];
#pragma unroll
    for (int q = 0; q < 4; q++) {
        float4 o;
        int pix = r * 64 + cs + q * 4;
        o.x = accAll[q * 4 + 0] + mean * gbase[3 * HW + pix + 0];
        o.y = accAll[q * 4 + 1] + mean * gbase[3 * HW + pix + 1];
        o.z = accAll[q * 4 + 2] + mean * gbase[3 * HW + pix + 2];
        o.w = accAll[q * 4 + 3] + mean * gbase[3 * HW + pix + 3];
        *(float4*)&dst[q * 4] = o;
    }
}

// =====================================================================
// K3: key logits  klog[b,n] = key_b + sum_c key_w[c]*ctx_all[b,c,n]
// =====================================================================
__global__ __launch_bounds__(256) void k_keylogit(const float* __restrict__ key_w,
                                                  const float* __restrict__ key_b) {
    __shared__ float kw[C];
    const int tid = threadIdx.x;
    kw[tid] = key_w[tid];
    __syncthreads();
    const int b = blockIdx.x >> 4;
    const int n = ((blockIdx.x & 15) << 8) + tid;
    const float* p = &g_ctxall[((b * C) << 12) + n];
    float acc = key_b[0];
#pragma unroll 8
    for (int c = 0; c < C; c++) acc += kw[c] * p[c << 12];
    g_klog[(b << 12) + n] = acc;
}

// =====================================================================
// K4: softmax over HW per batch
// =====================================================================
__global__ __launch_bounds__(256) void k_softmax() {
    __shared__ float red[8];
    const int b = blockIdx.x, tid = threadIdx.x;
    const float* p = &g_klog[b << 12];
    float v[16];
    float m = -1e30f;
#pragma unroll
    for (int i = 0; i < 16; i++) { v[i] = p[tid + (i << 8)]; m = fmaxf(m, v[i]); }
    for (int off = 16; off; off >>= 1) m = fmaxf(m, __shfl_xor_sync(0xffffffffu, m, off));
    if ((tid & 31) == 0) red[tid >> 5] = m;
    __syncthreads();
    float bm = red[0];
#pragma unroll
    for (int i = 1; i < 8; i++) bm = fmaxf(bm, red[i]);
    __syncthreads();
    float s = 0.f;
#pragma unroll
    for (int i = 0; i < 16; i++) { v[i] = expf(v[i] - bm); s += v[i]; }
    for (int off = 16; off; off >>= 1) s += __shfl_xor_sync(0xffffffffu, s, off);
    if ((tid & 31) == 0) red[tid >> 5] = s;
    __syncthreads();
    float tot = 0.f;
#pragma unroll
    for (int i = 0; i < 8; i++) tot += red[i];
    const float inv = 1.f / tot;
    float* o = &g_k[b << 12];
#pragma unroll
    for (int i = 0; i < 16; i++) o[tid + (i << 8)] = v[i] * inv;
}

// =====================================================================
// K5: qk[b,c] = sum_n ctx_all[b,c,n] * k[b,n]
// =====================================================================
__global__ __launch_bounds__(256) void k_qk() {
    __shared__ float sRed[8];
    const int tid = threadIdx.x;
    const int bc = blockIdx.x;                 // = b*C + c
    const float* p = &g_ctxall[bc << 12];
    const float* kp = &g_k[(bc >> 8) << 12];
    float acc = 0.f;
#pragma unroll
    for (int i = 0; i < 16; i++) {
        int n = tid + (i << 8);
        acc += p[n] * kp[n];
    }
    for (int off = 16; off; off >>= 1) acc += __shfl_xor_sync(0xffffffffu, acc, off);
    if ((tid & 31) == 0) sRed[tid >> 5] = acc;
    __syncthreads();
    if (tid == 0) {
        float t = 0.f;
#pragma unroll
        for (int i = 0; i < 8; i++) t += sRed[i];
        g_qk[bc] = t;
    }
}

// =====================================================================
// K6: v = v2( relu( LN( v1(qk) ) ) )  — tiny, one CTA
// =====================================================================
__global__ __launch_bounds__(256) void k_vmlp(const float* __restrict__ v1_w,
                                              const float* __restrict__ v1_b,
                                              const float* __restrict__ ln_w,
                                              const float* __restrict__ ln_b,
                                              const float* __restrict__ v2_w,
                                              const float* __restrict__ v2_b) {
    __shared__ float sqk[B * C];
    __shared__ float sv[B * 16];
    const int tid = threadIdx.x;
    for (int i = tid; i < B * C; i += 256) sqk[i] = g_qk[i];
    __syncthreads();
    const int b = tid >> 4, j = tid & 15;      // 16 batches x 16 out-channels
    float acc = v1_b[j];
#pragma unroll 4
    for (int c = 0; c < C; c++) acc += v1_w[j * C + c] * sqk[b * C + c];
    // LayerNorm over the 16 channels of this batch (16-lane shuffle group)
    float mu = acc;
    for (int off = 8; off; off >>= 1) mu += __shfl_xor_sync(0xffffffffu, mu, off);
    mu *= (1.f / 16.f);
    float d = acc - mu;
    float var = d * d;
    for (int off = 8; off; off >>= 1) var += __shfl_xor_sync(0xffffffffu, var, off);
    var *= (1.f / 16.f);
    float vn = d * rsqrtf(var + 1e-5f);
    vn = vn * ln_w[j] + ln_b[j];
    vn = fmaxf(vn, 0.f);
    sv[tid] = vn;
    __syncthreads();
    // v2: each thread emits 16 output channels for its batch
    const int b2 = tid >> 4;
    const int jo = tid & 15;
#pragma unroll
    for (int i = 0; i < 16; i++) {
        int co = jo + (i << 4);
        float a = v2_b[co];
#pragma unroll
        for (int jj = 0; jj < 16; jj++) a += v2_w[co * 16 + jj] * sv[b2 * 16 + jj];
        g_v[b2 * C + co] = a;
    }
}

// =====================================================================
// K7: out = ctx_all + v (broadcast over H,W)
// =====================================================================
__global__ __launch_bounds__(256) void k_final(float* __restrict__ out) {
    const int idx4 = blockIdx.x * 256 + threadIdx.x;   // float4 index
    const int base = idx4 << 2;
    const int bc = base >> 12;
    const float vv = g_v[bc];
    float4 t = *(const float4*)&g_ctxall[base];
    t.x += vv; t.y += vv; t.z += vv; t.w += vv;
    *(float4*)&out[base] = t;
}

// =====================================================================
extern "C" void kernel_launch(void* const* d_in, const int* in_sizes, int n_in,
                              void* d_out, int out_size) {
    const float* x      = (const float*)d_in[0];
    const float* conv_w = (const float*)d_in[1];
    const float* conv_b = (const float*)d_in[2];
    const float* fw3    = (const float*)d_in[3];
    const float* fw5    = (const float*)d_in[4];
    const float* fw7    = (const float*)d_in[5];
    const float* key_w  = (const float*)d_in[6];
    const float* key_b  = (const float*)d_in[7];
    const float* v1_w   = (const float*)d_in[8];
    const float* v1_b   = (const float*)d_in[9];
    const float* ln_w   = (const float*)d_in[10];
    const float* ln_b   = (const float*)d_in[11];
    const float* v2_w   = (const float*)d_in[12];
    const float* v2_b   = (const float*)d_in[13];

    k_conv1x1<<<1024, 256>>>(x, conv_w, conv_b);
    k_dwchain<<<4096, 256>>>(fw3, fw5, fw7);
    k_keylogit<<<256, 256>>>(key_w, key_b);
    k_softmax<<<16, 256>>>();
    k_qk<<<4096, 256>>>();
    k_vmlp<<<1, 256>>>(v1_w, v1_b, ln_w, ln_b, v2_w, v2_b);
    k_final<<<16384, 256>>>((float*)d_out);
}

// round 2
// speedup vs baseline: 1.4151x; 1.4151x over previous
#include <cuda_runtime.h>
#include <math.h>

#define HW   4096
#define WD   64
#define C    256
#define B    16
#define NO   260   // 256 ctx channels + 4 gate channels
#define KC   16

// ---------------- scratch (static device globals; no allocs) ----------------
__device__ float g_t[B * NO * HW];       // conv1x1 output: ctx(256) + gates(4)
__device__ float g_ctxall[B * C * HW];   // ctx_all
__device__ float g_klog[B * HW];
__device__ float g_k[B * HW];
__device__ float g_qk[B * C];
__device__ float g_v[B * C];

// ---------------- f32x2 helpers (FFMA2: 2 fp32 FMA per instruction) ---------
__device__ __forceinline__ unsigned long long pk2(float lo, float hi) {
    unsigned long long r;
    asm("mov.b64 %0,{%1,%2};" : "=l"(r) : "f"(lo), "f"(hi));
    return r;
}
__device__ __forceinline__ void upk2(unsigned long long v, float& lo, float& hi) {
    asm("mov.b64 {%0,%1},%2;" : "=f"(lo), "=f"(hi) : "l"(v));
}
__device__ __forceinline__ void fma2(unsigned long long& d, unsigned long long a,
                                     unsigned long long b) {
    asm("fma.rn.f32x2 %0,%1,%2,%0;" : "+l"(d) : "l"(a), "l"(b));
}

// ---------------- cp.async helpers -----------------------------------------
__device__ __forceinline__ unsigned s2u(const void* p) {
    return (unsigned)__cvta_generic_to_shared(p);
}
__device__ __forceinline__ void cp16(unsigned dst, const void* src) {
    asm volatile("cp.async.ca.shared.global [%0], [%1], 16;" :: "r"(dst), "l"(src));
}
__device__ __forceinline__ void cp4(unsigned dst, const void* src) {
    asm volatile("cp.async.ca.shared.global [%0], [%1], 4;" :: "r"(dst), "l"(src));
}
#define CP_COMMIT() asm volatile("cp.async.commit_group;")
#define CP_WAIT1()  asm volatile("cp.async.wait_group 1;")

// =====================================================================
// K1: conv1x1  t[b,o,hw] = sum_c x[b,c,hw]*w[o,c] + bias[o]
// CTA tile: 64 outputs (+4 gates on ot==3) x 256 pixels.
// Thread: 8 outputs x 8 pixels (4 f32x2 accums per output).
// Weights staged transposed [k][o] -> warp-broadcast LDS (free).
// x staged [k][256 px] -> conflict-free float4 LDS.
// cp.async double-buffered chunks of KC=16 k.
// =====================================================================
template<bool G>
__device__ __forceinline__ void chunk_compute(
    const float* __restrict__ xs,   // [KC][256]
    const float* __restrict__ ws,   // [KC][68]
    int tx, int ty,
    unsigned long long acc[8][4], unsigned long long accg[4])
{
#pragma unroll
    for (int k = 0; k < KC; k++) {
        const float4 xa = *(const float4*)&xs[k * 256 + tx * 4];
        const float4 xb = *(const float4*)&xs[k * 256 + 128 + tx * 4];
        unsigned long long x0 = pk2(xa.x, xa.y), x1 = pk2(xa.z, xa.w);
        unsigned long long x2 = pk2(xb.x, xb.y), x3 = pk2(xb.z, xb.w);
        const float4 w0 = *(const float4*)&ws[k * 68 + ty * 8];
        const float4 w1 = *(const float4*)&ws[k * 68 + ty * 8 + 4];
        const float wv[8] = {w0.x, w0.y, w0.z, w0.w, w1.x, w1.y, w1.z, w1.w};
#pragma unroll
        for (int j = 0; j < 8; j++) {
            unsigned long long wp = pk2(wv[j], wv[j]);
            fma2(acc[j][0], x0, wp);
            fma2(acc[j][1], x1, wp);
            fma2(acc[j][2], x2, wp);
            fma2(acc[j][3], x3, wp);
        }
        if (G) {
            float gw = ws[k * 68 + 64 + (ty & 3)];
            unsigned long long gp = pk2(gw, gw);
            fma2(accg[0], x0, gp);
            fma2(accg[1], x1, gp);
            fma2(accg[2], x2, gp);
            fma2(accg[3], x3, gp);
        }
    }
}

__device__ __forceinline__ void stage_chunk(
    unsigned xs_s, unsigned ws_s,
    const float* __restrict__ x, const float* __restrict__ w,
    int b, int pix0, int ot, int k0, int tid)
{
#pragma unroll
    for (int it = 0; it < 4; it++) {
        int i = tid + it * 256;
        int row = i >> 6, col = (i & 63) << 2;
        cp16(xs_s + (unsigned)((row * 256 + col) * 4),
             x + (((b * C + k0 + row) << 12) + pix0 + col));
    }
#pragma unroll
    for (int it = 0; it < 5; it++) {
        int i = tid + it * 256;
        if (i < 68 * KC) {
            int o = i >> 4, kk = i & 15;
            cp4(ws_s + (unsigned)((kk * 68 + o) * 4),
                w + ((ot * 64 + o) * C + k0 + kk));
        }
    }
}

__global__ __launch_bounds__(256, 2) void k_conv1x1(const float* __restrict__ x,
                                                    const float* __restrict__ w,
                                                    const float* __restrict__ bias) {
    __shared__ float xs[2][KC * 256];
    __shared__ float ws[2][KC * 68];
    const int tid = threadIdx.x;
    const int tx = tid & 31;         // pixel group
    const int ty = tid >> 5;         // output group (0..7)
    const int ot   = blockIdx.x & 3;
    const int pix0 = ((blockIdx.x >> 2) & 15) << 8;
    const int b    = blockIdx.x >> 6;

    unsigned long long acc[8][4];
    unsigned long long accg[4] = {0ull, 0ull, 0ull, 0ull};
#pragma unroll
    for (int j = 0; j < 8; j++) { acc[j][0] = acc[j][1] = acc[j][2] = acc[j][3] = 0ull; }

    stage_chunk(s2u(xs[0]), s2u(ws[0]), x, w, b, pix0, ot, 0, tid);
    CP_COMMIT();

    for (int c = 0; c < 16; c++) {
        if (c < 15)
            stage_chunk(s2u(xs[(c + 1) & 1]), s2u(ws[(c + 1) & 1]),
                        x, w, b, pix0, ot, (c + 1) * KC, tid);
        CP_COMMIT();
        CP_WAIT1();
        __syncthreads();
        if (ot == 3)
            chunk_compute<true>(xs[c & 1], ws[c & 1], tx, ty, acc, accg);
        else
            chunk_compute<false>(xs[c & 1], ws[c & 1], tx, ty, acc, accg);
        __syncthreads();
    }

    const int obase = ot * 64 + ty * 8;
#pragma unroll
    for (int j = 0; j < 8; j++) {
        float bv = bias[obase + j];
        float4 r0, r1;
        upk2(acc[j][0], r0.x, r0.y); upk2(acc[j][1], r0.z, r0.w);
        upk2(acc[j][2], r1.x, r1.y); upk2(acc[j][3], r1.z, r1.w);
        r0.x += bv; r0.y += bv; r0.z += bv; r0.w += bv;
        r1.x += bv; r1.y += bv; r1.z += bv; r1.w += bv;
        float* dst = &g_t[((b * NO + obase + j) << 12) + pix0];
        *(float4*)&dst[tx * 4] = r0;
        *(float4*)&dst[128 + tx * 4] = r1;
    }
    if (ot == 3) {
        int go = 256 + (ty & 3);
        float bv = bias[go];
        float4 r0, r1;
        upk2(accg[0], r0.x, r0.y); upk2(accg[1], r0.z, r0.w);
        upk2(accg[2], r1.x, r1.y); upk2(accg[3], r1.z, r1.w);
        r0.x += bv; r0.y += bv; r0.z += bv; r0.w += bv;
        r1.x += bv; r1.y += bv; r1.z += bv; r1.w += bv;
        float* dst = &g_t[((b * NO + go) << 12) + pix0];
        // ty and ty+4 write identical values (benign duplicate store)
        *(float4*)&dst[tx * 4] = r0;
        *(float4*)&dst[128 + tx * 4] = r1;
    }
}

// =====================================================================
// K2: fused dw3->gelu -> dw5->gelu -> dw7->gelu chain + gated accumulate
//     + global-context term, one CTA per (b, channel) 64x64 plane.
// PST=71 (odd) + warp = 16 rows x 2 strips  ->  bank-conflict-free LDS.
// =====================================================================
__device__ __forceinline__ float gelu_exact(float v) {
    return 0.5f * v * (1.f + erff(v * 0.70710678118654752440f));
}

#define PST 71   // padded row stride (70 rows x 71 cols, halo = 3); odd -> no bank conflicts

template <int KS>
__device__ __forceinline__ void stage(const float* __restrict__ s_in,
                                      float* __restrict__ s_out,
                                      const float* __restrict__ sW,
                                      int r, int cs) {
    const int P = KS / 2;
    float acc[16];
#pragma unroll
    for (int i = 0; i < 16; i++) acc[i] = 0.f;
#pragma unroll
    for (int dy = 0; dy < KS; dy++) {
        float row[16 + 2 * (KS / 2)];
        const float* rp = &s_in[(r + 3 + dy - P) * PST + (cs + 3 - P)];
#pragma unroll
        for (int i = 0; i < 16 + 2 * P; i++) row[i] = rp[i];
#pragma unroll
        for (int dx = 0; dx < KS; dx++) {
            float wv = sW[dy * KS + dx];
#pragma unroll
            for (int i = 0; i < 16; i++) acc[i] += row[i + dx] * wv;
        }
    }
    float* op = &s_out[(r + 3) * PST + cs + 3];
#pragma unroll
    for (int i = 0; i < 16; i++) op[i] = gelu_exact(acc[i]);
}

__global__ __launch_bounds__(256) void k_dwchain(const float* __restrict__ fw3,
                                                 const float* __restrict__ fw5,
                                                 const float* __restrict__ fw7) {
    __shared__ float sA[70 * PST];
    __shared__ float sB[70 * PST];
    __shared__ float sW[49];
    __shared__ float sRed[8];
    const int tid = threadIdx.x;
    const int b  = blockIdx.x >> 8;
    const int ch = blockIdx.x & 255;
    // warp = 16 consecutive rows x 2 strips  ->  bank = (7*lr + 16*lc) mod 32, injective
    const int wrp  = tid >> 5;
    const int lane = tid & 31;
    const int lr = lane >> 1, lc = lane & 1;
    const int r  = (wrp & 3) * 16 + lr;              // 0..63
    const int cs = (((wrp >> 2) << 1) + lc) << 4;    // 0,16,32,48

    for (int i = tid; i < 70 * PST; i += 256) { sA[i] = 0.f; sB[i] = 0.f; }
    __syncthreads();

    const float* src = &g_t[(b * NO + ch) << 12];
#pragma unroll
    for (int i = 0; i < 16; i++) {
        int idx = tid + i * 256;
        int rr = idx >> 6, cc = idx & 63;
        sA[(rr + 3) * PST + cc + 3] = src[idx];
    }

    const float* gbase = &g_t[(b * NO + C) << 12];  // gate planes, 4 x 4096
    float accAll[16];
#pragma unroll
    for (int i = 0; i < 16; i++) accAll[i] = 0.f;

    // ---- stage 1: 3x3 ----
    if (tid < 9) sW[tid] = fw3[ch * 9 + tid];
    __syncthreads();
    stage<3>(sA, sB, sW, r, cs);
#pragma unroll
    for (int i = 0; i < 16; i++) {
        int pix = r * 64 + cs + i;
        accAll[i] += sB[(r + 3) * PST + cs + 3 + i] * gbase[pix];
    }
    __syncthreads();
    // ---- stage 2: 5x5 ----
    if (tid < 25) sW[tid] = fw5[ch * 25 + tid];
    __syncthreads();
    stage<5>(sB, sA, sW, r, cs);
#pragma unroll
    for (int i = 0; i < 16; i++) {
        int pix = r * 64 + cs + i;
        accAll[i] += sA[(r + 3) * PST + cs + 3 + i] * gbase[HW + pix];
    }
    __syncthreads();
    // ---- stage 3: 7x7 ----
    if (tid < 49) sW[tid] = fw7[ch * 49 + tid];
    __syncthreads();
    stage<7>(sA, sB, sW, r, cs);
    float lsum = 0.f;
#pragma unroll
    for (int i = 0; i < 16; i++) {
        int pix = r * 64 + cs + i;
        float v = sB[(r + 3) * PST + cs + 3 + i];
        accAll[i] += v * gbase[2 * HW + pix];
        lsum += v;
    }
    // block reduce lsum -> mean of final ctx plane
    for (int off = 16; off; off >>= 1)
        lsum += __shfl_xor_sync(0xffffffffu, lsum, off);
    if ((tid & 31) == 0) sRed[tid >> 5] = lsum;
    __syncthreads();
    float tot = 0.f;
#pragma unroll
    for (int i = 0; i < 8; i++) tot += sRed[i];
    const float mean = tot * (1.f / 4096.f);

    float* dst = &g_ctxall[((b * C + ch) << 12) + r * 64 + cs];
#pragma unroll
    for (int q = 0; q < 4; q++) {
        float4 o;
        int pix = r * 64 + cs + q * 4;
        o.x = accAll[q * 4 + 0] + mean * gbase[3 * HW + pix + 0];
        o.y = accAll[q * 4 + 1] + mean * gbase[3 * HW + pix + 1];
        o.z = accAll[q * 4 + 2] + mean * gbase[3 * HW + pix + 2];
        o.w = accAll[q * 4 + 3] + mean * gbase[3 * HW + pix + 3];
        *(float4*)&dst[q * 4] = o;
    }
}

// =====================================================================
// K3: key logits  klog[b,n] = key_b + sum_c key_w[c]*ctx_all[b,c,n]
// =====================================================================
__global__ __launch_bounds__(256) void k_keylogit(const float* __restrict__ key_w,
                                                  const float* __restrict__ key_b) {
    __shared__ float kw[C];
    const int tid = threadIdx.x;
    kw[tid] = key_w[tid];
    __syncthreads();
    const int b = blockIdx.x >> 4;
    const int n = ((blockIdx.x & 15) << 8) + tid;
    const float* p = &g_ctxall[((b * C) << 12) + n];
    float acc = key_b[0];
#pragma unroll 8
    for (int c = 0; c < C; c++) acc += kw[c] * p[c << 12];
    g_klog[(b << 12) + n] = acc;
}

// =====================================================================
// K4: softmax over HW per batch
// =====================================================================
__global__ __launch_bounds__(256) void k_softmax() {
    __shared__ float red[8];
    const int b = blockIdx.x, tid = threadIdx.x;
    const float* p = &g_klog[b << 12];
    float v[16];
    float m = -1e30f;
#pragma unroll
    for (int i = 0; i < 16; i++) { v[i] = p[tid + (i << 8)]; m = fmaxf(m, v[i]); }
    for (int off = 16; off; off >>= 1) m = fmaxf(m, __shfl_xor_sync(0xffffffffu, m, off));
    if ((tid & 31) == 0) red[tid >> 5] = m;
    __syncthreads();
    float bm = red[0];
#pragma unroll
    for (int i = 1; i < 8; i++) bm = fmaxf(bm, red[i]);
    __syncthreads();
    float s = 0.f;
#pragma unroll
    for (int i = 0; i < 16; i++) { v[i] = expf(v[i] - bm); s += v[i]; }
    for (int off = 16; off; off >>= 1) s += __shfl_xor_sync(0xffffffffu, s, off);
    if ((tid & 31) == 0) red[tid >> 5] = s;
    __syncthreads();
    float tot = 0.f;
#pragma unroll
    for (int i = 0; i < 8; i++) tot += red[i];
    const float inv = 1.f / tot;
    float* o = &g_k[b << 12];
#pragma unroll
    for (int i = 0; i < 16; i++) o[tid + (i << 8)] = v[i] * inv;
}

// =====================================================================
// K5: qk[b,c] = sum_n ctx_all[b,c,n] * k[b,n]
// =====================================================================
__global__ __launch_bounds__(256) void k_qk() {
    __shared__ float sRed[8];
    const int tid = threadIdx.x;
    const int bc = blockIdx.x;                 // = b*C + c
    const float* p = &g_ctxall[bc << 12];
    const float* kp = &g_k[(bc >> 8) << 12];
    float acc = 0.f;
#pragma unroll
    for (int i = 0; i < 16; i++) {
        int n = tid + (i << 8);
        acc += p[n] * kp[n];
    }
    for (int off = 16; off; off >>= 1) acc += __shfl_xor_sync(0xffffffffu, acc, off);
    if ((tid & 31) == 0) sRed[tid >> 5] = acc;
    __syncthreads();
    if (tid == 0) {
        float t = 0.f;
#pragma unroll
        for (int i = 0; i < 8; i++) t += sRed[i];
        g_qk[bc] = t;
    }
}

// =====================================================================
// K6: v = v2( relu( LN( v1(qk) ) ) )  — tiny, one CTA
// =====================================================================
__global__ __launch_bounds__(256) void k_vmlp(const float* __restrict__ v1_w,
                                              const float* __restrict__ v1_b,
                                              const float* __restrict__ ln_w,
                                              const float* __restrict__ ln_b,
                                              const float* __restrict__ v2_w,
                                              const float* __restrict__ v2_b) {
    __shared__ float sqk[B * C];
    __shared__ float sv[B * 16];
    const int tid = threadIdx.x;
    for (int i = tid; i < B * C; i += 256) sqk[i] = g_qk[i];
    __syncthreads();
    const int b = tid >> 4, j = tid & 15;      // 16 batches x 16 out-channels
    float acc = v1_b[j];
#pragma unroll 4
    for (int c = 0; c < C; c++) acc += v1_w[j * C + c] * sqk[b * C + c];
    // LayerNorm over the 16 channels of this batch (16-lane shuffle group)
    float mu = acc;
    for (int off = 8; off; off >>= 1) mu += __shfl_xor_sync(0xffffffffu, mu, off);
    mu *= (1.f / 16.f);
    float d = acc - mu;
    float var = d * d;
    for (int off = 8; off; off >>= 1) var += __shfl_xor_sync(0xffffffffu, var, off);
    var *= (1.f / 16.f);
    float vn = d * rsqrtf(var + 1e-5f);
    vn = vn * ln_w[j] + ln_b[j];
    vn = fmaxf(vn, 0.f);
    sv[tid] = vn;
    __syncthreads();
    // v2: each thread emits 16 output channels for its batch
    const int b2 = tid >> 4;
    const int jo = tid & 15;
#pragma unroll
    for (int i = 0; i < 16; i++) {
        int co = jo + (i << 4);
        float a = v2_b[co];
#pragma unroll
        for (int jj = 0; jj < 16; jj++) a += v2_w[co * 16 + jj] * sv[b2 * 16 + jj];
        g_v[b2 * C + co] = a;
    }
}

// =====================================================================
// K7: out = ctx_all + v (broadcast over H,W)
// =====================================================================
__global__ __launch_bounds__(256) void k_final(float* __restrict__ out) {
    const int idx4 = blockIdx.x * 256 + threadIdx.x;   // float4 index
    const int base = idx4 << 2;
    const int bc = base >> 12;
    const float vv = g_v[bc];
    float4 t = *(const float4*)&g_ctxall[base];
    t.x += vv; t.y += vv; t.z += vv; t.w += vv;
    *(float4*)&out[base] = t;
}

// =====================================================================
extern "C" void kernel_launch(void* const* d_in, const int* in_sizes, int n_in,
                              void* d_out, int out_size) {
    const float* x      = (const float*)d_in[0];
    const float* conv_w = (const float*)d_in[1];
    const float* conv_b = (const float*)d_in[2];
    const float* fw3    = (const float*)d_in[3];
    const float* fw5    = (const float*)d_in[4];
    const float* fw7    = (const float*)d_in[5];
    const float* key_w  = (const float*)d_in[6];
    const float* key_b  = (const float*)d_in[7];
    const float* v1_w   = (const float*)d_in[8];
    const float* v1_b   = (const float*)d_in[9];
    const float* ln_w   = (const float*)d_in[10];
    const float* ln_b   = (const float*)d_in[11];
    const float* v2_w   = (const float*)d_in[12];
    const float* v2_b   = (const float*)d_in[13];

    k_conv1x1<<<1024, 256>>>(x, conv_w, conv_b);
    k_dwchain<<<4096, 256>>>(fw3, fw5, fw7);
    k_keylogit<<<256, 256>>>(key_w, key_b);
    k_softmax<<<16, 256>>>();
    k_qk<<<4096, 256>>>();
    k_vmlp<<<1, 256>>>(v1_w, v1_b, ln_w, ln_b, v2_w, v2_b);
    k_final<<<16384, 256>>>((float*)d_out);
}

// round 5
// speedup vs baseline: 1.4293x; 1.0100x over previous
#include <cuda_runtime.h>
#include <cuda_bf16.h>
#include <mma.h>
#include <math.h>
#include <stdint.h>

using namespace nvcuda;

#define HW   4096
#define WD   64
#define C    256
#define B    16
#define NO   260   // 256 ctx channels + 4 gate channels

// ---------------- scratch (static device globals; no allocs) ----------------
__device__ float g_t[B * NO * HW];       // conv1x1 output: ctx(256, NO bias) + gates(4, biased)
__device__ float g_ctxall[B * C * HW];   // ctx_all
__device__ float g_klog[B * HW];
__device__ float g_k[B * HW];
__device__ float g_qk[B * C];
__device__ float g_v[B * C];
__device__ __align__(16) __nv_bfloat16 g_wh[C * C];      // w hi split (ctx rows)
__device__ __align__(16) __nv_bfloat16 g_wl[C * C];      // w lo split
__device__ __align__(16) __nv_bfloat16 g_xh[B * C * HW]; // x hi split
__device__ __align__(16) __nv_bfloat16 g_xl[B * C * HW]; // x lo split

// ---------------- cp.async helpers -----------------------------------------
__device__ __forceinline__ unsigned s2u(const void* p) {
    return (unsigned)__cvta_generic_to_shared(p);
}
__device__ __forceinline__ void cp16(unsigned dst, const void* src) {
    asm volatile("cp.async.ca.shared.global [%0], [%1], 16;" :: "r"(dst), "l"(src));
}
#define CP_COMMIT() asm volatile("cp.async.commit_group;")
#define CP_WAIT1()  asm volatile("cp.async.wait_group 1;")

// =====================================================================
// K0a: split w (ctx rows 0..255) into bf16 hi/lo
// =====================================================================
__global__ __launch_bounds__(256) void k_wsplit(const float* __restrict__ w) {
    int idx = blockIdx.x * 256 + threadIdx.x;   // grid 256 -> 65536
    float v = w[idx];
    __nv_bfloat16 h = __float2bfloat16(v);
    g_wh[idx] = h;
    g_wl[idx] = __float2bfloat16(v - __bfloat162float(h));
}

// =====================================================================
// K0b: split x into bf16 hi/lo (streaming)
// =====================================================================
__global__ __launch_bounds__(256) void k_xsplit(const float* __restrict__ x) {
    size_t i4 = (size_t)blockIdx.x * 256 + threadIdx.x;  // float4 index
    float4 v = ((const float4*)x)[i4];
    __nv_bfloat16 h0 = __float2bfloat16(v.x), h1 = __float2bfloat16(v.y);
    __nv_bfloat16 h2 = __float2bfloat16(v.z), h3 = __float2bfloat16(v.w);
    __nv_bfloat162 hp0 = {h0, h1}, hp1 = {h2, h3};
    __nv_bfloat162 lp0 = {__float2bfloat16(v.x - __bfloat162float(h0)),
                          __float2bfloat16(v.y - __bfloat162float(h1))};
    __nv_bfloat162 lp1 = {__float2bfloat16(v.z - __bfloat162float(h2)),
                          __float2bfloat16(v.w - __bfloat162float(h3))};
    uint2 hv = {*(uint32_t*)&hp0, *(uint32_t*)&hp1};
    uint2 lv = {*(uint32_t*)&lp0, *(uint32_t*)&lp1};
    *(uint2*)&g_xh[i4 * 4] = hv;
    *(uint2*)&g_xl[i4 * 4] = lv;
}

// =====================================================================
// K1: wmma bf16 GEMM  t[b,o,px] = sum_c w[o,c]*x[b,c,px]  (bias folded later)
// CTA = (b, o-half of 128, 128-px window). 8 warps, warp tile 64x32.
// A = w [o][c] row-major, B = x [c][px] row-major (natural!). 3-product split.
// K chunks of 32, cp.async double-buffered. Strides 40/136 -> conflict-free LDSM.
// SMEM buffer (bf16 elems): AH 128x40=5120 | AL 5120 | BH 32x136=4352 | BL 4352
// =====================================================================
#define BUF_ELEMS 18944
#define OFF_AL 5120
#define OFF_BH 10240
#define OFF_BL 14592
#define GEMM_SMEM (2 * BUF_ELEMS * 2)   // 75776 bytes

__global__ __launch_bounds__(256, 2) void k_gemm() {
    extern __shared__ __align__(16) __nv_bfloat16 sm[];
    const int tid = threadIdx.x;
    const int wid = tid >> 5;
    const int bx = blockIdx.x;
    const int pw = bx & 31, oh = (bx >> 5) & 1, b = bx >> 6;
    const int px0 = pw << 7, o0 = oh << 7;
    const int wm = wid & 1, wn = wid >> 1;   // warp tile: m = wm*64, n = wn*32

    wmma::fragment<wmma::accumulator, 16, 16, 16, float> acc[4][2];
#pragma unroll
    for (int i = 0; i < 4; i++)
#pragma unroll
        for (int j = 0; j < 2; j++) wmma::fill_fragment(acc[i][j], 0.f);

    // ---- staging ----
    auto stage = [&](int ci) {
        unsigned base = s2u(sm + (ci & 1) * BUF_ELEMS);
        const int k0 = ci << 5;
#pragma unroll
        for (int v = 0; v < 2; v++) {
            const __nv_bfloat16* wsrc = v ? g_wl : g_wh;
#pragma unroll
            for (int it = 0; it < 2; it++) {
                int idx = tid + it * 256;            // 0..511
                int o = idx >> 2, u = idx & 3;
                cp16(base + (unsigned)((v * OFF_AL + o * 40 + u * 8) * 2),
                     wsrc + (o0 + o) * 256 + k0 + u * 8);
            }
        }
#pragma unroll
        for (int v = 0; v < 2; v++) {
            const __nv_bfloat16* xsrc = v ? g_xl : g_xh;
#pragma unroll
            for (int it = 0; it < 2; it++) {
                int idx = tid + it * 256;            // 0..511
                int k = idx >> 4, u = idx & 15;
                cp16(base + (unsigned)((OFF_BH + v * 4352 + k * 136 + u * 8) * 2),
                     xsrc + (((size_t)(b * C + k0 + k)) << 12) + px0 + u * 8);
            }
        }
    };

    auto compute = [&](int ci) {
        const __nv_bfloat16* bufp = sm + (ci & 1) * BUF_ELEMS;
        const __nv_bfloat16* AH = bufp;
        const __nv_bfloat16* AL = bufp + OFF_AL;
        const __nv_bfloat16* BH = bufp + OFF_BH;
        const __nv_bfloat16* BL = bufp + OFF_BL;
#pragma unroll
        for (int kk = 0; kk < 2; kk++) {
            wmma::fragment<wmma::matrix_a, 16, 16, 16, __nv_bfloat16, wmma::row_major> af[4];
            wmma::fragment<wmma::matrix_b, 16, 16, 16, __nv_bfloat16, wmma::row_major> bhf[2], blf[2];
#pragma unroll
            for (int j = 0; j < 2; j++)
                wmma::load_matrix_sync(bhf[j], BH + kk * 16 * 136 + wn * 32 + j * 16, 136);
#pragma unroll
            for (int i = 0; i < 4; i++)
                wmma::load_matrix_sync(af[i], AH + (wm * 64 + i * 16) * 40 + kk * 16, 40);
#pragma unroll
            for (int i = 0; i < 4; i++)
#pragma unroll
                for (int j = 0; j < 2; j++)
                    wmma::mma_sync(acc[i][j], af[i], bhf[j], acc[i][j]);
#pragma unroll
            for (int j = 0; j < 2; j++)
                wmma::load_matrix_sync(blf[j], BL + kk * 16 * 136 + wn * 32 + j * 16, 136);
#pragma unroll
            for (int i = 0; i < 4; i++)
#pragma unroll
                for (int j = 0; j < 2; j++)
                    wmma::mma_sync(acc[i][j], af[i], blf[j], acc[i][j]);
#pragma unroll
            for (int i = 0; i < 4; i++)
                wmma::load_matrix_sync(af[i], AL + (wm * 64 + i * 16) * 40 + kk * 16, 40);
#pragma unroll
            for (int i = 0; i < 4; i++)
#pragma unroll
                for (int j = 0; j < 2; j++)
                    wmma::mma_sync(acc[i][j], af[i], bhf[j], acc[i][j]);
        }
    };

    stage(0);
    CP_COMMIT();
    for (int ci = 0; ci < 8; ci++) {
        if (ci < 7) stage(ci + 1);
        CP_COMMIT();
        CP_WAIT1();
        __syncthreads();
        compute(ci);
        __syncthreads();
    }

    // ---- epilogue: direct wmma stores (no bias; bias folded into k_dwchain) ----
#pragma unroll
    for (int i = 0; i < 4; i++)
#pragma unroll
        for (int j = 0; j < 2; j++)
            wmma::store_matrix_sync(
                g_t + (((size_t)(b * NO + o0 + wm * 64 + i * 16)) << 12) + px0 + wn * 32 + j * 16,
                acc[i][j], HW, wmma::mem_row_major);
}

// =====================================================================
// K1b: gate outputs (o = 256..259), streaming fp32 (bias included)
// =====================================================================
__global__ __launch_bounds__(256) void k_gates(const float* __restrict__ x,
                                               const float* __restrict__ w,
                                               const float* __restrict__ bias) {
    __shared__ float wg[C][4];
    const int tid = threadIdx.x;
    for (int i = tid; i < C * 4; i += 256) {
        int c = i >> 2, j = i & 3;
        wg[c][j] = w[(256 + j) * C + c];
    }
    __syncthreads();
    const int b = blockIdx.x >> 4;
    const int px = ((blockIdx.x & 15) << 8) + tid;
    const float* p = x + (((size_t)(b * C)) << 12) + px;
    float a0 = 0.f, a1 = 0.f, a2 = 0.f, a3 = 0.f;
#pragma unroll 8
    for (int c = 0; c < C; c++) {
        float xv = p[(size_t)c << 12];
        a0 += xv * wg[c][0];
        a1 += xv * wg[c][1];
        a2 += xv * wg[c][2];
        a3 += xv * wg[c][3];
    }
    g_t[(((size_t)(b * NO + 256)) << 12) + px] = a0 + bias[256];
    g_t[(((size_t)(b * NO + 257)) << 12) + px] = a1 + bias[257];
    g_t[(((size_t)(b * NO + 258)) << 12) + px] = a2 + bias[258];
    g_t[(((size_t)(b * NO + 259)) << 12) + px] = a3 + bias[259];
}

// =====================================================================
// K2: fused dw3->gelu -> dw5->gelu -> dw7->gelu chain + gated accumulate
//     + global-context term, one CTA per (b, channel) 64x64 plane.
//     NOTE: adds conv bias[ch] to the plane on load (GEMM skips bias).
// =====================================================================
__device__ __forceinline__ float gelu_exact(float v) {
    return 0.5f * v * (1.f + erff(v * 0.70710678118654752440f));
}

#define PST 71

template <int KS>
__device__ __forceinline__ void stage_dw(const float* __restrict__ s_in,
                                         float* __restrict__ s_out,
                                         const float* __restrict__ sW,
                                         int r, int cs) {
    const int P = KS / 2;
    float acc[16];
#pragma unroll
    for (int i = 0; i < 16; i++) acc[i] = 0.f;
#pragma unroll
    for (int dy = 0; dy < KS; dy++) {
        float row[16 + 2 * (KS / 2)];
        const float* rp = &s_in[(r + 3 + dy - P) * PST + (cs + 3 - P)];
#pragma unroll
        for (int i = 0; i < 16 + 2 * P; i++) row[i] = rp[i];
#pragma unroll
        for (int dx = 0; dx < KS; dx++) {
            float wv = sW[dy * KS + dx];
#pragma unroll
            for (int i = 0; i < 16; i++) acc[i] += row[i + dx] * wv;
        }
    }
    float* op = &s_out[(r + 3) * PST + cs + 3];
#pragma unroll
    for (int i = 0; i < 16; i++) op[i] = gelu_exact(acc[i]);
}

__global__ __launch_bounds__(256) void k_dwchain(const float* __restrict__ fw3,
                                                 const float* __restrict__ fw5,
                                                 const float* __restrict__ fw7,
                                                 const float* __restrict__ cb) {
    __shared__ float sA[70 * PST];
    __shared__ float sB[70 * PST];
    __shared__ float sW[49];
    __shared__ float sRed[8];
    const int tid = threadIdx.x;
    const int b  = blockIdx.x >> 8;
    const int ch = blockIdx.x & 255;
    const int wrp  = tid >> 5;
    const int lane = tid & 31;
    const int lr = lane >> 1, lc = lane & 1;
    const int r  = (wrp & 3) * 16 + lr;
    const int cs = (((wrp >> 2) << 1) + lc) << 4;

    for (int i = tid; i < 70 * PST; i += 256) { sA[i] = 0.f; sB[i] = 0.f; }
    __syncthreads();

    const float bv = cb[ch];
    const float* src = &g_t[(size_t)(b * NO + ch) << 12];
#pragma unroll
    for (int i = 0; i < 16; i++) {
        int idx = tid + i * 256;
        int rr = idx >> 6, cc = idx & 63;
        sA[(rr + 3) * PST + cc + 3] = src[idx] + bv;
    }

    const float* gbase = &g_t[(size_t)(b * NO + C) << 12];
    float accAll[16];
#pragma unroll
    for (int i = 0; i < 16; i++) accAll[i] = 0.f;

    if (tid < 9) sW[tid] = fw3[ch * 9 + tid];
    __syncthreads();
    stage_dw<3>(sA, sB, sW, r, cs);
#pragma unroll
    for (int i = 0; i < 16; i++) {
        int pix = r * 64 + cs + i;
        accAll[i] += sB[(r + 3) * PST + cs + 3 + i] * gbase[pix];
    }
    __syncthreads();
    if (tid < 25) sW[tid] = fw5[ch * 25 + tid];
    __syncthreads();
    stage_dw<5>(sB, sA, sW, r, cs);
#pragma unroll
    for (int i = 0; i < 16; i++) {
        int pix = r * 64 + cs + i;
        accAll[i] += sA[(r + 3) * PST + cs + 3 + i] * gbase[HW + pix];
    }
    __syncthreads();
    if (tid < 49) sW[tid] = fw7[ch * 49 + tid];
    __syncthreads();
    stage_dw<7>(sA, sB, sW, r, cs);
    float lsum = 0.f;
#pragma unroll
    for (int i = 0; i < 16; i++) {
        int pix = r * 64 + cs + i;
        float v = sB[(r + 3) * PST + cs + 3 + i];
        accAll[i] += v * gbase[2 * HW + pix];
        lsum += v;
    }
    for (int off = 16; off; off >>= 1)
        lsum += __shfl_xor_sync(0xffffffffu, lsum, off);
    if ((tid & 31) == 0) sRed[tid >> 5] = lsum;
    __syncthreads();
    float tot = 0.f;
#pragma unroll
    for (int i = 0; i < 8; i++) tot += sRed[i];
    const float mean = tot * (1.f / 4096.f);

    float* dst = &g_ctxall[((size_t)(b * C + ch) << 12) + r * 64 + cs];
#pragma unroll
    for (int q = 0; q < 4; q++) {
        float4 o;
        int pix = r * 64 + cs + q * 4;
        o.x = accAll[q * 4 + 0] + mean * gbase[3 * HW + pix + 0];
        o.y = accAll[q * 4 + 1] + mean * gbase[3 * HW + pix + 1];
        o.z = accAll[q * 4 + 2] + mean * gbase[3 * HW + pix + 2];
        o.w = accAll[q * 4 + 3] + mean * gbase[3 * HW + pix + 3];
        *(float4*)&dst[q * 4] = o;
    }
}

// =====================================================================
// K3: key logits
// =====================================================================
__global__ __launch_bounds__(256) void k_keylogit(const float* __restrict__ key_w,
                                                  const float* __restrict__ key_b) {
    __shared__ float kw[C];
    const int tid = threadIdx.x;
    kw[tid] = key_w[tid];
    __syncthreads();
    const int b = blockIdx.x >> 4;
    const int n = ((blockIdx.x & 15) << 8) + tid;
    const float* p = &g_ctxall[((size_t)(b * C) << 12) + n];
    float acc = key_b[0];
#pragma unroll 8
    for (int c = 0; c < C; c++) acc += kw[c] * p[(size_t)c << 12];
    g_klog[(b << 12) + n] = acc;
}

// =====================================================================
// K4: softmax over HW per batch
// =====================================================================
__global__ __launch_bounds__(256) void k_softmax() {
    __shared__ float red[8];
    const int b = blockIdx.x, tid = threadIdx.x;
    const float* p = &g_klog[b << 12];
    float v[16];
    float m = -1e30f;
#pragma unroll
    for (int i = 0; i < 16; i++) { v[i] = p[tid + (i << 8)]; m = fmaxf(m, v[i]); }
    for (int off = 16; off; off >>= 1) m = fmaxf(m, __shfl_xor_sync(0xffffffffu, m, off));
    if ((tid & 31) == 0) red[tid >> 5] = m;
    __syncthreads();
    float bm = red[0];
#pragma unroll
    for (int i = 1; i < 8; i++) bm = fmaxf(bm, red[i]);
    __syncthreads();
    float s = 0.f;
#pragma unroll
    for (int i = 0; i < 16; i++) { v[i] = expf(v[i] - bm); s += v[i]; }
    for (int off = 16; off; off >>= 1) s += __shfl_xor_sync(0xffffffffu, s, off);
    if ((tid & 31) == 0) red[tid >> 5] = s;
    __syncthreads();
    float tot = 0.f;
#pragma unroll
    for (int i = 0; i < 8; i++) tot += red[i];
    const float inv = 1.f / tot;
    float* o = &g_k[b << 12];
#pragma unroll
    for (int i = 0; i < 16; i++) o[tid + (i << 8)] = v[i] * inv;
}

// =====================================================================
// K5: qk[b,c] = sum_n ctx_all[b,c,n] * k[b,n]
// =====================================================================
__global__ __launch_bounds__(256) void k_qk() {
    __shared__ float sRed[8];
    const int tid = threadIdx.x;
    const int bc = blockIdx.x;
    const float* p = &g_ctxall[(size_t)bc << 12];
    const float* kp = &g_k[(bc >> 8) << 12];
    float acc = 0.f;
#pragma unroll
    for (int i = 0; i < 16; i++) {
        int n = tid + (i << 8);
        acc += p[n] * kp[n];
    }
    for (int off = 16; off; off >>= 1) acc += __shfl_xor_sync(0xffffffffu, acc, off);
    if ((tid & 31) == 0) sRed[tid >> 5] = acc;
    __syncthreads();
    if (tid == 0) {
        float t = 0.f;
#pragma unroll
        for (int i = 0; i < 8; i++) t += sRed[i];
        g_qk[bc] = t;
    }
}

// =====================================================================
// K6: v = v2( relu( LN( v1(qk) ) ) )
// =====================================================================
__global__ __launch_bounds__(256) void k_vmlp(const float* __restrict__ v1_w,
                                              const float* __restrict__ v1_b,
                                              const float* __restrict__ ln_w,
                                              const float* __restrict__ ln_b,
                                              const float* __restrict__ v2_w,
                                              const float* __restrict__ v2_b) {
    __shared__ float sqk[B * C];
    __shared__ float sv[B * 16];
    const int tid = threadIdx.x;
    for (int i = tid; i < B * C; i += 256) sqk[i] = g_qk[i];
    __syncthreads();
    const int b = tid >> 4, j = tid & 15;
    float acc = v1_b[j];
#pragma unroll 4
    for (int c = 0; c < C; c++) acc += v1_w[j * C + c] * sqk[b * C + c];
    float mu = acc;
    for (int off = 8; off; off >>= 1) mu += __shfl_xor_sync(0xffffffffu, mu, off);
    mu *= (1.f / 16.f);
    float d = acc - mu;
    float var = d * d;
    for (int off = 8; off; off >>= 1) var += __shfl_xor_sync(0xffffffffu, var, off);
    var *= (1.f / 16.f);
    float vn = d * rsqrtf(var + 1e-5f);
    vn = vn * ln_w[j] + ln_b[j];
    vn = fmaxf(vn, 0.f);
    sv[tid] = vn;
    __syncthreads();
    const int b2 = tid >> 4;
    const int jo = tid & 15;
#pragma unroll
    for (int i = 0; i < 16; i++) {
        int co = jo + (i << 4);
        float a = v2_b[co];
#pragma unroll
        for (int jj = 0; jj < 16; jj++) a += v2_w[co * 16 + jj] * sv[b2 * 16 + jj];
        g_v[b2 * C + co] = a;
    }
}

// =====================================================================
// K7: out = ctx_all + v (broadcast over H,W)
// =====================================================================
__global__ __launch_bounds__(256) void k_final(float* __restrict__ out) {
    const int idx4 = blockIdx.x * 256 + threadIdx.x;
    const size_t base = (size_t)idx4 << 2;
    const int bc = (int)(base >> 12);
    const float vv = g_v[bc];
    float4 t = *(const float4*)&g_ctxall[base];
    t.x += vv; t.y += vv; t.z += vv; t.w += vv;
    *(float4*)&out[base] = t;
}

// =====================================================================
extern "C" void kernel_launch(void* const* d_in, const int* in_sizes, int n_in,
                              void* d_out, int out_size) {
    const float* x      = (const float*)d_in[0];
    const float* conv_w = (const float*)d_in[1];
    const float* conv_b = (const float*)d_in[2];
    const float* fw3    = (const float*)d_in[3];
    const float* fw5    = (const float*)d_in[4];
    const float* fw7    = (const float*)d_in[5];
    const float* key_w  = (const float*)d_in[6];
    const float* key_b  = (const float*)d_in[7];
    const float* v1_w   = (const float*)d_in[8];
    const float* v1_b   = (const float*)d_in[9];
    const float* ln_w   = (const float*)d_in[10];
    const float* ln_b   = (const float*)d_in[11];
    const float* v2_w   = (const float*)d_in[12];
    const float* v2_b   = (const float*)d_in[13];

    static bool attr_set = false;
    if (!attr_set) {
        cudaFuncSetAttribute(k_gemm, cudaFuncAttributeMaxDynamicSharedMemorySize, GEMM_SMEM);
        attr_set = true;
    }

    k_wsplit<<<256, 256>>>(conv_w);
    k_xsplit<<<16384, 256>>>(x);
    k_gemm<<<1024, 256, GEMM_SMEM>>>();
    k_gates<<<256, 256>>>(x, conv_w, conv_b);
    k_dwchain<<<4096, 256>>>(fw3, fw5, fw7, conv_b);
    k_keylogit<<<256, 256>>>(key_w, key_b);
    k_softmax<<<16, 256>>>();
    k_qk<<<4096, 256>>>();
    k_vmlp<<<1, 256>>>(v1_w, v1_b, ln_w, ln_b, v2_w, v2_b);
    k_final<<<16384, 256>>>((float*)d_out);
}

// round 6
// speedup vs baseline: 1.8830x; 1.3174x over previous
#include <cuda_runtime.h>
#include <cuda_bf16.h>
#include <mma.h>
#include <math.h>
#include <stdint.h>

using namespace nvcuda;

#define HW   4096
#define WD   64
#define C    256
#define B    16
#define NO   260   // 256 ctx channels + 4 gate channels

// ---------------- scratch (static device globals; no allocs) ----------------
__device__ float g_t[B * NO * HW];       // conv1x1 output: ctx(256, no bias) + gates(4, biased)
__device__ float g_ctxall[B * C * HW];   // ctx_all
__device__ float g_klog[B * HW];
__device__ float g_k[B * HW];
__device__ float g_qk[B * C];
__device__ float g_v[B * C];
__device__ __align__(16) __nv_bfloat16 g_wh[C * C];      // w hi split (ctx rows)
__device__ __align__(16) __nv_bfloat16 g_wl[C * C];      // w lo split

// ---------------- cp.async helpers -----------------------------------------
__device__ __forceinline__ unsigned s2u(const void* p) {
    return (unsigned)__cvta_generic_to_shared(p);
}
__device__ __forceinline__ void cp16(unsigned dst, const void* src) {
    asm volatile("cp.async.ca.shared.global [%0], [%1], 16;" :: "r"(dst), "l"(src));
}
#define CP_COMMIT() asm volatile("cp.async.commit_group;")
#define CP_WAIT1()  asm volatile("cp.async.wait_group 1;")

// =====================================================================
// K0: split w (ctx rows 0..255) into bf16 hi/lo
// =====================================================================
__global__ __launch_bounds__(256) void k_wsplit(const float* __restrict__ w) {
    int idx = blockIdx.x * 256 + threadIdx.x;   // grid 256 -> 65536
    float v = w[idx];
    __nv_bfloat16 h = __float2bfloat16(v);
    g_wh[idx] = h;
    g_wl[idx] = __float2bfloat16(v - __bfloat162float(h));
}

// =====================================================================
// K1: wmma bf16 GEMM  t[b,o,px] = sum_c w[o,c]*x[b,c,px]  (bias folded later)
// CTA = (b, o-half of 128, 128-px window). 8 warps, warp tile 64x32.
// A = w (pre-split bf16, cp.async). B = x fp32 -> in-kernel hi/lo split:
//   LDG.128 reg prefetch (next chunk) overlapped with compute, cvt+STS here.
// K chunks of 32, double-buffered. Strides 40/136 -> conflict-free LDSM.
// SMEM buffer (bf16 elems): AH 128x40=5120 | AL 5120 | BH 32x136=4352 | BL 4352
// =====================================================================
#define BUF_ELEMS 18944
#define OFF_AL 5120
#define OFF_BH 10240
#define OFF_BL 14592
#define GEMM_SMEM (2 * BUF_ELEMS * 2)   // 75776 bytes

__global__ __launch_bounds__(256, 2) void k_gemm(const float* __restrict__ x) {
    extern __shared__ __align__(16) __nv_bfloat16 sm[];
    const int tid = threadIdx.x;
    const int wid = tid >> 5;
    const int bx = blockIdx.x;
    const int pw = bx & 31, oh = (bx >> 5) & 1, b = bx >> 6;
    const int px0 = pw << 7, o0 = oh << 7;
    const int wm = wid & 1, wn = wid >> 1;   // warp tile: m = wm*64, n = wn*32

    wmma::fragment<wmma::accumulator, 16, 16, 16, float> acc[4][2];
#pragma unroll
    for (int i = 0; i < 4; i++)
#pragma unroll
        for (int j = 0; j < 2; j++) wmma::fill_fragment(acc[i][j], 0.f);

    // ---- A staging via cp.async (w already bf16 split) ----
    auto stageA = [&](int ci) {
        unsigned base = s2u(sm + (ci & 1) * BUF_ELEMS);
        const int k0 = ci << 5;
#pragma unroll
        for (int v = 0; v < 2; v++) {
            const __nv_bfloat16* wsrc = v ? g_wl : g_wh;
#pragma unroll
            for (int it = 0; it < 2; it++) {
                int idx = tid + it * 256;            // 0..511
                int o = idx >> 2, u = idx & 3;
                cp16(base + (unsigned)((v * OFF_AL + o * 40 + u * 8) * 2),
                     wsrc + (o0 + o) * 256 + k0 + u * 8);
            }
        }
    };

    // ---- B: LDG fp32 into regs ----
    auto ldx = [&](float4* R, int ci) {
        const int k0 = ci << 5;
#pragma unroll
        for (int it = 0; it < 4; it++) {
            int fi = it * 256 + tid;                 // 0..1023 float4s (32k x 32)
            int k = fi >> 5, u = fi & 31;
            R[it] = *(const float4*)(x + (((size_t)(b * C + k0 + k)) << 12) + px0 + u * 4);
        }
    };
    // ---- B: convert + store hi/lo bf16 to smem ----
    auto stsB = [&](const float4* R, int buf) {
        __nv_bfloat16* bp = sm + buf * BUF_ELEMS;
#pragma unroll
        for (int it = 0; it < 4; it++) {
            int fi = it * 256 + tid;
            int k = fi >> 5, u = fi & 31;
            float4 v = R[it];
            __nv_bfloat16 h0 = __float2bfloat16(v.x), h1 = __float2bfloat16(v.y);
            __nv_bfloat16 h2 = __float2bfloat16(v.z), h3 = __float2bfloat16(v.w);
            __nv_bfloat162 hp0 = {h0, h1}, hp1 = {h2, h3};
            __nv_bfloat162 lp0 = {__float2bfloat16(v.x - __bfloat162float(h0)),
                                  __float2bfloat16(v.y - __bfloat162float(h1))};
            __nv_bfloat162 lp1 = {__float2bfloat16(v.z - __bfloat162float(h2)),
                                  __float2bfloat16(v.w - __bfloat162float(h3))};
            uint2 hv = {*(uint32_t*)&hp0, *(uint32_t*)&hp1};
            uint2 lv = {*(uint32_t*)&lp0, *(uint32_t*)&lp1};
            *(uint2*)(bp + OFF_BH + k * 136 + u * 4) = hv;
            *(uint2*)(bp + OFF_BL + k * 136 + u * 4) = lv;
        }
    };

    auto compute = [&](int ci) {
        const __nv_bfloat16* bufp = sm + (ci & 1) * BUF_ELEMS;
        const __nv_bfloat16* AH = bufp;
        const __nv_bfloat16* AL = bufp + OFF_AL;
        const __nv_bfloat16* BH = bufp + OFF_BH;
        const __nv_bfloat16* BL = bufp + OFF_BL;
#pragma unroll
        for (int kk = 0; kk < 2; kk++) {
            wmma::fragment<wmma::matrix_a, 16, 16, 16, __nv_bfloat16, wmma::row_major> af[4];
            wmma::fragment<wmma::matrix_b, 16, 16, 16, __nv_bfloat16, wmma::row_major> bhf[2], blf[2];
#pragma unroll
            for (int j = 0; j < 2; j++)
                wmma::load_matrix_sync(bhf[j], BH + kk * 16 * 136 + wn * 32 + j * 16, 136);
#pragma unroll
            for (int i = 0; i < 4; i++)
                wmma::load_matrix_sync(af[i], AH + (wm * 64 + i * 16) * 40 + kk * 16, 40);
#pragma unroll
            for (int i = 0; i < 4; i++)
#pragma unroll
                for (int j = 0; j < 2; j++)
                    wmma::mma_sync(acc[i][j], af[i], bhf[j], acc[i][j]);
#pragma unroll
            for (int j = 0; j < 2; j++)
                wmma::load_matrix_sync(blf[j], BL + kk * 16 * 136 + wn * 32 + j * 16, 136);
#pragma unroll
            for (int i = 0; i < 4; i++)
#pragma unroll
                for (int j = 0; j < 2; j++)
                    wmma::mma_sync(acc[i][j], af[i], blf[j], acc[i][j]);
#pragma unroll
            for (int i = 0; i < 4; i++)
                wmma::load_matrix_sync(af[i], AL + (wm * 64 + i * 16) * 40 + kk * 16, 40);
#pragma unroll
            for (int i = 0; i < 4; i++)
#pragma unroll
                for (int j = 0; j < 2; j++)
                    wmma::mma_sync(acc[i][j], af[i], bhf[j], acc[i][j]);
        }
    };

    float4 R[4];
    stageA(0);
    CP_COMMIT();
    ldx(R, 0);
    for (int ci = 0; ci < 8; ci++) {
        if (ci < 7) stageA(ci + 1);
        CP_COMMIT();           // (possibly empty group; keeps WAIT1 semantics)
        CP_WAIT1();            // A(ci) resident
        stsB(R, ci & 1);
        __syncthreads();       // A + B tiles visible to all
        if (ci < 7) ldx(R, ci + 1);   // overlap next-chunk LDG with compute
        compute(ci);
        __syncthreads();
    }

    // ---- epilogue: direct wmma stores (bias folded into k_dwchain) ----
#pragma unroll
    for (int i = 0; i < 4; i++)
#pragma unroll
        for (int j = 0; j < 2; j++)
            wmma::store_matrix_sync(
                g_t + (((size_t)(b * NO + o0 + wm * 64 + i * 16)) << 12) + px0 + wn * 32 + j * 16,
                acc[i][j], HW, wmma::mem_row_major);
}

// =====================================================================
// K1b: gate outputs (o = 256..259). Channel reduction split 4-way per px
// (grid 1024, smem tree-reduce) for latency hiding.
// =====================================================================
__global__ __launch_bounds__(256) void k_gates(const float* __restrict__ x,
                                               const float* __restrict__ w,
                                               const float* __restrict__ bias) {
    __shared__ float wg[C][4];
    __shared__ float red[4][4][64];
    const int tid = threadIdx.x;
    for (int i = tid; i < C * 4; i += 256) {
        int c = i >> 2, j = i & 3;
        wg[c][j] = w[(256 + j) * C + c];
    }
    __syncthreads();
    const int b   = blockIdx.x >> 6;
    const int px0 = (blockIdx.x & 63) << 6;
    const int pxi = tid & 63;
    const int q   = tid >> 6;         // channel quarter
    const float* p = x + (((size_t)(b * C + q * 64)) << 12) + px0 + pxi;
    float a0 = 0.f, a1 = 0.f, a2 = 0.f, a3 = 0.f;
#pragma unroll 8
    for (int c = 0; c < 64; c++) {
        float xv = p[(size_t)c << 12];
        a0 += xv * wg[q * 64 + c][0];
        a1 += xv * wg[q * 64 + c][1];
        a2 += xv * wg[q * 64 + c][2];
        a3 += xv * wg[q * 64 + c][3];
    }
    red[q][0][pxi] = a0;
    red[q][1][pxi] = a1;
    red[q][2][pxi] = a2;
    red[q][3][pxi] = a3;
    __syncthreads();
    if (q == 0) {
#pragma unroll
        for (int j = 0; j < 4; j++) {
            float s = red[0][j][pxi] + red[1][j][pxi] + red[2][j][pxi] + red[3][j][pxi]
                      + bias[256 + j];
            g_t[(((size_t)(b * NO + 256 + j)) << 12) + px0 + pxi] = s;
        }
    }
}

// =====================================================================
// K2: fused dw3->gelu -> dw5->gelu -> dw7->gelu chain + gated accumulate
//     + global-context term, one CTA per (b, channel) 64x64 plane.
//     Adds conv bias[ch] on plane load (GEMM skips bias). Gate loads float4.
// =====================================================================
__device__ __forceinline__ float gelu_exact(float v) {
    return 0.5f * v * (1.f + erff(v * 0.70710678118654752440f));
}

#define PST 71

template <int KS>
__device__ __forceinline__ void stage_dw(const float* __restrict__ s_in,
                                         float* __restrict__ s_out,
                                         const float* __restrict__ sW,
                                         int r, int cs) {
    const int P = KS / 2;
    float acc[16];
#pragma unroll
    for (int i = 0; i < 16; i++) acc[i] = 0.f;
#pragma unroll
    for (int dy = 0; dy < KS; dy++) {
        float row[16 + 2 * (KS / 2)];
        const float* rp = &s_in[(r + 3 + dy - P) * PST + (cs + 3 - P)];
#pragma unroll
        for (int i = 0; i < 16 + 2 * P; i++) row[i] = rp[i];
#pragma unroll
        for (int dx = 0; dx < KS; dx++) {
            float wv = sW[dy * KS + dx];
#pragma unroll
            for (int i = 0; i < 16; i++) acc[i] += row[i + dx] * wv;
        }
    }
    float* op = &s_out[(r + 3) * PST + cs + 3];
#pragma unroll
    for (int i = 0; i < 16; i++) op[i] = gelu_exact(acc[i]);
}

__global__ __launch_bounds__(256) void k_dwchain(const float* __restrict__ fw3,
                                                 const float* __restrict__ fw5,
                                                 const float* __restrict__ fw7,
                                                 const float* __restrict__ cb) {
    __shared__ float sA[70 * PST];
    __shared__ float sB[70 * PST];
    __shared__ float sW[49];
    __shared__ float sRed[8];
    const int tid = threadIdx.x;
    const int b  = blockIdx.x >> 8;
    const int ch = blockIdx.x & 255;
    const int wrp  = tid >> 5;
    const int lane = tid & 31;
    const int lr = lane >> 1, lc = lane & 1;
    const int r  = (wrp & 3) * 16 + lr;
    const int cs = (((wrp >> 2) << 1) + lc) << 4;

    for (int i = tid; i < 70 * PST; i += 256) { sA[i] = 0.f; sB[i] = 0.f; }
    __syncthreads();

    const float bv = cb[ch];
    const float* src = &g_t[(size_t)(b * NO + ch) << 12];
#pragma unroll
    for (int i = 0; i < 16; i++) {
        int idx = tid + i * 256;
        int rr = idx >> 6, cc = idx & 63;
        sA[(rr + 3) * PST + cc + 3] = src[idx] + bv;
    }

    const float* gbase = &g_t[(size_t)(b * NO + C) << 12];
    float accAll[16];
#pragma unroll
    for (int i = 0; i < 16; i++) accAll[i] = 0.f;

    if (tid < 9) sW[tid] = fw3[ch * 9 + tid];
    __syncthreads();
    stage_dw<3>(sA, sB, sW, r, cs);
#pragma unroll
    for (int f = 0; f < 4; f++) {
        float4 gv = *(const float4*)(gbase + r * 64 + cs + f * 4);
        accAll[f * 4 + 0] += sB[(r + 3) * PST + cs + 3 + f * 4 + 0] * gv.x;
        accAll[f * 4 + 1] += sB[(r + 3) * PST + cs + 3 + f * 4 + 1] * gv.y;
        accAll[f * 4 + 2] += sB[(r + 3) * PST + cs + 3 + f * 4 + 2] * gv.z;
        accAll[f * 4 + 3] += sB[(r + 3) * PST + cs + 3 + f * 4 + 3] * gv.w;
    }
    __syncthreads();
    if (tid < 25) sW[tid] = fw5[ch * 25 + tid];
    __syncthreads();
    stage_dw<5>(sB, sA, sW, r, cs);
#pragma unroll
    for (int f = 0; f < 4; f++) {
        float4 gv = *(const float4*)(gbase + HW + r * 64 + cs + f * 4);
        accAll[f * 4 + 0] += sA[(r + 3) * PST + cs + 3 + f * 4 + 0] * gv.x;
        accAll[f * 4 + 1] += sA[(r + 3) * PST + cs + 3 + f * 4 + 1] * gv.y;
        accAll[f * 4 + 2] += sA[(r + 3) * PST + cs + 3 + f * 4 + 2] * gv.z;
        accAll[f * 4 + 3] += sA[(r + 3) * PST + cs + 3 + f * 4 + 3] * gv.w;
    }
    __syncthreads();
    if (tid < 49) sW[tid] = fw7[ch * 49 + tid];
    __syncthreads();
    stage_dw<7>(sA, sB, sW, r, cs);
    float lsum = 0.f;
#pragma unroll
    for (int f = 0; f < 4; f++) {
        float4 gv = *(const float4*)(gbase + 2 * HW + r * 64 + cs + f * 4);
        float v0 = sB[(r + 3) * PST + cs + 3 + f * 4 + 0];
        float v1 = sB[(r + 3) * PST + cs + 3 + f * 4 + 1];
        float v2 = sB[(r + 3) * PST + cs + 3 + f * 4 + 2];
        float v3 = sB[(r + 3) * PST + cs + 3 + f * 4 + 3];
        accAll[f * 4 + 0] += v0 * gv.x;
        accAll[f * 4 + 1] += v1 * gv.y;
        accAll[f * 4 + 2] += v2 * gv.z;
        accAll[f * 4 + 3] += v3 * gv.w;
        lsum += v0 + v1 + v2 + v3;
    }
    for (int off = 16; off; off >>= 1)
        lsum += __shfl_xor_sync(0xffffffffu, lsum, off);
    if ((tid & 31) == 0) sRed[tid >> 5] = lsum;
    __syncthreads();
    float tot = 0.f;
#pragma unroll
    for (int i = 0; i < 8; i++) tot += sRed[i];
    const float mean = tot * (1.f / 4096.f);

    float* dst = &g_ctxall[((size_t)(b * C + ch) << 12) + r * 64 + cs];
#pragma unroll
    for (int f = 0; f < 4; f++) {
        float4 gv = *(const float4*)(gbase + 3 * HW + r * 64 + cs + f * 4);
        float4 o;
        o.x = accAll[f * 4 + 0] + mean * gv.x;
        o.y = accAll[f * 4 + 1] + mean * gv.y;
        o.z = accAll[f * 4 + 2] + mean * gv.z;
        o.w = accAll[f * 4 + 3] + mean * gv.w;
        *(float4*)&dst[f * 4] = o;
    }
}

// =====================================================================
// K3: key logits
// =====================================================================
__global__ __launch_bounds__(256) void k_keylogit(const float* __restrict__ key_w,
                                                  const float* __restrict__ key_b) {
    __shared__ float kw[C];
    const int tid = threadIdx.x;
    kw[tid] = key_w[tid];
    __syncthreads();
    const int b = blockIdx.x >> 4;
    const int n = ((blockIdx.x & 15) << 8) + tid;
    const float* p = &g_ctxall[((size_t)(b * C) << 12) + n];
    float acc = key_b[0];
#pragma unroll 8
    for (int c = 0; c < C; c++) acc += kw[c] * p[(size_t)c << 12];
    g_klog[(b << 12) + n] = acc;
}

// =====================================================================
// K4: softmax over HW per batch
// =====================================================================
__global__ __launch_bounds__(256) void k_softmax() {
    __shared__ float red[8];
    const int b = blockIdx.x, tid = threadIdx.x;
    const float* p = &g_klog[b << 12];
    float v[16];
    float m = -1e30f;
#pragma unroll
    for (int i = 0; i < 16; i++) { v[i] = p[tid + (i << 8)]; m = fmaxf(m, v[i]); }
    for (int off = 16; off; off >>= 1) m = fmaxf(m, __shfl_xor_sync(0xffffffffu, m, off));
    if ((tid & 31) == 0) red[tid >> 5] = m;
    __syncthreads();
    float bm = red[0];
#pragma unroll
    for (int i = 1; i < 8; i++) bm = fmaxf(bm, red[i]);
    __syncthreads();
    float s = 0.f;
#pragma unroll
    for (int i = 0; i < 16; i++) { v[i] = expf(v[i] - bm); s += v[i]; }
    for (int off = 16; off; off >>= 1) s += __shfl_xor_sync(0xffffffffu, s, off);
    if ((tid & 31) == 0) red[tid >> 5] = s;
    __syncthreads();
    float tot = 0.f;
#pragma unroll
    for (int i = 0; i < 8; i++) tot += red[i];
    const float inv = 1.f / tot;
    float* o = &g_k[b << 12];
#pragma unroll
    for (int i = 0; i < 16; i++) o[tid + (i << 8)] = v[i] * inv;
}

// =====================================================================
// K5: qk[b,c] = sum_n ctx_all[b,c,n] * k[b,n]
// =====================================================================
__global__ __launch_bounds__(256) void k_qk() {
    __shared__ float sRed[8];
    const int tid = threadIdx.x;
    const int bc = blockIdx.x;
    const float* p = &g_ctxall[(size_t)bc << 12];
    const float* kp = &g_k[(bc >> 8) << 12];
    float acc = 0.f;
#pragma unroll
    for (int i = 0; i < 16; i++) {
        int n = tid + (i << 8);
        acc += p[n] * kp[n];
    }
    for (int off = 16; off; off >>= 1) acc += __shfl_xor_sync(0xffffffffu, acc, off);
    if ((tid & 31) == 0) sRed[tid >> 5] = acc;
    __syncthreads();
    if (tid == 0) {
        float t = 0.f;
#pragma unroll
        for (int i = 0; i < 8; i++) t += sRed[i];
        g_qk[bc] = t;
    }
}

// =====================================================================
// K6: v = v2( relu( LN( v1(qk) ) ) )
// =====================================================================
__global__ __launch_bounds__(256) void k_vmlp(const float* __restrict__ v1_w,
                                              const float* __restrict__ v1_b,
                                              const float* __restrict__ ln_w,
                                              const float* __restrict__ ln_b,
                                              const float* __restrict__ v2_w,
                                              const float* __restrict__ v2_b) {
    __shared__ float sqk[B * C];
    __shared__ float sv[B * 16];
    const int tid = threadIdx.x;
    for (int i = tid; i < B * C; i += 256) sqk[i] = g_qk[i];
    __syncthreads();
    const int b = tid >> 4, j = tid & 15;
    float acc = v1_b[j];
#pragma unroll 4
    for (int c = 0; c < C; c++) acc += v1_w[j * C + c] * sqk[b * C + c];
    float mu = acc;
    for (int off = 8; off; off >>= 1) mu += __shfl_xor_sync(0xffffffffu, mu, off);
    mu *= (1.f / 16.f);
    float d = acc - mu;
    float var = d * d;
    for (int off = 8; off; off >>= 1) var += __shfl_xor_sync(0xffffffffu, var, off);
    var *= (1.f / 16.f);
    float vn = d * rsqrtf(var + 1e-5f);
    vn = vn * ln_w[j] + ln_b[j];
    vn = fmaxf(vn, 0.f);
    sv[tid] = vn;
    __syncthreads();
    const int b2 = tid >> 4;
    const int jo = tid & 15;
#pragma unroll
    for (int i = 0; i < 16; i++) {
        int co = jo + (i << 4);
        float a = v2_b[co];
#pragma unroll
        for (int jj = 0; jj < 16; jj++) a += v2_w[co * 16 + jj] * sv[b2 * 16 + jj];
        g_v[b2 * C + co] = a;
    }
}

// =====================================================================
// K7: out = ctx_all + v (broadcast over H,W)
// =====================================================================
__global__ __launch_bounds__(256) void k_final(float* __restrict__ out) {
    const int idx4 = blockIdx.x * 256 + threadIdx.x;
    const size_t base = (size_t)idx4 << 2;
    const int bc = (int)(base >> 12);
    const float vv = g_v[bc];
    float4 t = *(const float4*)&g_ctxall[base];
    t.x += vv; t.y += vv; t.z += vv; t.w += vv;
    *(float4*)&out[base] = t;
}

// =====================================================================
extern "C" void kernel_launch(void* const* d_in, const int* in_sizes, int n_in,
                              void* d_out, int out_size) {
    const float* x      = (const float*)d_in[0];
    const float* conv_w = (const float*)d_in[1];
    const float* conv_b = (const float*)d_in[2];
    const float* fw3    = (const float*)d_in[3];
    const float* fw5    = (const float*)d_in[4];
    const float* fw7    = (const float*)d_in[5];
    const float* key_w  = (const float*)d_in[6];
    const float* key_b  = (const float*)d_in[7];
    const float* ln_w   = (const float*)d_in[10];
    const float* ln_b   = (const float*)d_in[11];
    const float* v1_w   = (const float*)d_in[8];
    const float* v1_b   = (const float*)d_in[9];
    const float* v2_w   = (const float*)d_in[12];
    const float* v2_b   = (const float*)d_in[13];

    static bool attr_set = false;
    if (!attr_set) {
        cudaFuncSetAttribute(k_gemm, cudaFuncAttributeMaxDynamicSharedMemorySize, GEMM_SMEM);
        attr_set = true;
    }

    k_wsplit<<<256, 256>>>(conv_w);
    k_gemm<<<1024, 256, GEMM_SMEM>>>(x);
    k_gates<<<1024, 256>>>(x, conv_w, conv_b);
    k_dwchain<<<4096, 256>>>(fw3, fw5, fw7, conv_b);
    k_keylogit<<<256, 256>>>(key_w, key_b);
    k_softmax<<<16, 256>>>();
    k_qk<<<4096, 256>>>();
    k_vmlp<<<1, 256>>>(v1_w, v1_b, ln_w, ln_b, v2_w, v2_b);
    k_final<<<16384, 256>>>((float*)d_out);
}